// round 12
// baseline (speedup 1.0000x reference)
#include <cuda_runtime.h>
#include <cstdint>
#include <math.h>

#define T_TOK 16384
#define H_DIM 1024
#define F_DIM 512
#define E_NUM 64
#define TK    (T_TOK * 2)            // 32768 routed pairs
#define BM    128
#define MAX_TILES (TK / BM + E_NUM)  // 320
#define PCH   20                     // f32 smem pitch: conflict-free LDSM

// rounding-pass ranges (float4 units)
#define N4_HID (T_TOK * H_DIM / 4)
#define N4_WGU (E_NUM * 2 * F_DIM * H_DIM / 4)
#define N4_WD  (E_NUM * H_DIM * F_DIM / 4)
#define N4_ALL (N4_HID + N4_WGU + N4_WD)

// -------------------- static device scratch --------------------
__device__ int   g_offset[E_NUM];
__device__ int   g_cursor[E_NUM];
__device__ int   g_pair_token[TK];
__device__ float g_pair_w[TK];
__device__ int   g_pos_of[TK];
__device__ int   g_num_tiles;
__device__ int   g_tile_e[MAX_TILES];
__device__ int   g_tile_row[MAX_TILES];
__device__ int   g_tile_rows[MAX_TILES];

__device__ __align__(16) float g_hid[(size_t)T_TOK * H_DIM];            // tf32-rounded
__device__ __align__(16) float g_wgu[(size_t)E_NUM * 2 * F_DIM * H_DIM];
__device__ __align__(16) float g_wd [(size_t)E_NUM * H_DIM * F_DIM];
__device__ __align__(16) float g_act[(size_t)TK * F_DIM];               // tf32-rounded
__device__ __align__(16) float g_y  [(size_t)TK * H_DIM];

// -------------------- helpers --------------------
__device__ __forceinline__ float t32(float x) {
    uint32_t u;
    asm("cvt.rna.tf32.f32 %0, %1;" : "=r"(u) : "f"(x));
    return __uint_as_float(u);
}
__device__ __forceinline__ float silu_mul(float g, float u) {
    return g / (1.f + __expf(-g)) * u;
}
__device__ __forceinline__ uint32_t smem_u32(const void* p) {
    uint32_t a;
    asm("{ .reg .u64 t; cvta.to.shared.u64 t, %1; cvt.u32.u64 %0, t; }" : "=r"(a) : "l"(p));
    return a;
}

#define CP_ASYNC(dst, src) \
    asm volatile("cp.async.cg.shared.global [%0], [%1], 16;" :: "r"(dst), "l"(src))
#define CP_COMMIT() asm volatile("cp.async.commit_group;" ::: "memory")
#define CP_WAIT2()  asm volatile("cp.async.wait_group 2;" ::: "memory")
#define CP_WAIT0()  asm volatile("cp.async.wait_group 0;" ::: "memory")

#define LDSM4(r0, r1, r2, r3, addr) \
    asm volatile("ldmatrix.sync.aligned.m8n8.x4.shared.b16 {%0,%1,%2,%3}, [%4];" \
        : "=r"(r0), "=r"(r1), "=r"(r2), "=r"(r3) : "r"(addr))

#define MMA_TF32(c, a0, a1, a2, a3, b0, b1) \
    asm volatile("mma.sync.aligned.m16n8k8.row.col.f32.tf32.tf32.f32 " \
        "{%0,%1,%2,%3}, {%4,%5,%6,%7}, {%8,%9}, {%0,%1,%2,%3};" \
        : "+f"((c)[0]), "+f"((c)[1]), "+f"((c)[2]), "+f"((c)[3]) \
        : "r"(a0), "r"(a1), "r"(a2), "r"(a3), "r"(b0), "r"(b1))

// stage (f32): A [128][PCH] @ 0 ; W [128][PCH] @ 10240 B. Stage 20480 B x 4.
#define STG_BYTES 20480
#define SMEM_BYTES 81920

// -------------------- tf32 rounding pass --------------------
__global__ void k_round_all(const float* __restrict__ hidden,
                            const float* __restrict__ wgu,
                            const float* __restrict__ wd) {
    size_t i = (size_t)blockIdx.x * 256 + threadIdx.x;
    const float4* src;
    float* dst;
    size_t off;
    if (i < N4_HID)               { src = (const float4*)hidden; dst = g_hid; off = i; }
    else if (i < N4_HID + N4_WGU) { src = (const float4*)wgu;    dst = g_wgu; off = i - N4_HID; }
    else                          { src = (const float4*)wd;     dst = g_wd;  off = i - N4_HID - N4_WGU; }
    float4 v = src[off];
    float4 o = make_float4(t32(v.x), t32(v.y), t32(v.z), t32(v.w));
    *(float4*)(dst + off * 4) = o;
}

// -------------------- routing --------------------
__global__ void k_route(const int* __restrict__ ids) {
    __shared__ int hist[E_NUM];
    int tid = threadIdx.x;
    if (tid < E_NUM) hist[tid] = 0;
    __syncthreads();
    for (int i = tid; i < TK; i += 1024) atomicAdd(&hist[ids[i]], 1);
    __syncthreads();
    if (tid == 0) {
        int off = 0, nt = 0;
        for (int e = 0; e < E_NUM; e++) {
            g_offset[e] = off; g_cursor[e] = 0;
            int c = hist[e];
            for (int r = 0; r < c; r += BM) {
                g_tile_e[nt] = e;
                g_tile_row[nt] = off + r;
                g_tile_rows[nt] = (c - r < BM) ? (c - r) : BM;
                nt++;
            }
            off += c;
        }
        g_num_tiles = nt;
    }
}
__global__ void k_scatter(const int* __restrict__ ids, const float* __restrict__ w) {
    int i = blockIdx.x * blockDim.x + threadIdx.x;
    if (i < TK) {
        int e = ids[i];
        int pos = g_offset[e] + atomicAdd(&g_cursor[e], 1);
        g_pair_token[pos] = i >> 1;
        g_pair_w[pos] = w[i];
        g_pos_of[i] = pos;
    }
}

// ==================== GEMM1: act = silu(X Wg^T) * (X Wu^T) ====================
// grid(8, MAX_TILES), 128 thr (4 warps 2x2), 2 CTAs/SM.
// CTA 128 rows x (64 gate + 64 up). Warp tile 64x64. K=1024.
__global__ void __launch_bounds__(128, 2)
k_gemm1(const float* __restrict__ unused) {
    int tile = blockIdx.y;
    if (tile >= g_num_tiles) return;
    const int e = g_tile_e[tile], row0 = g_tile_row[tile], rows = g_tile_rows[tile];
    const int bx = blockIdx.x;

    extern __shared__ __align__(16) float fsm[];
    __shared__ int s_tok[BM];

    const int tid  = threadIdx.x;
    const int warp = tid >> 5, lane = tid & 31;
    const int wm = warp >> 1, wn = warp & 1;

    if (tid < BM) s_tok[tid] = g_pair_token[row0 + ((tid < rows) ? tid : 0)];
    __syncthreads();

    // ---- cp.async: thread handles rows arw+32p (p=0..3) for A and W, chunk c4
    const int arw = tid >> 2, c4 = (tid & 3) * 4;       // arw 0..31
    const float* pA[4];
    const float* pW[4];
    #pragma unroll
    for (int p = 0; p < 4; p++) {
        int rw = arw + 32 * p;
        pA[p] = g_hid + (size_t)s_tok[rw] * H_DIM + c4;
        int grow = bx * 64 + (rw & 63) + ((rw >= 64) ? F_DIM : 0);   // gate rows 0-63, up 64-127
        pW[p] = g_wgu + ((size_t)e * 2 * F_DIM + grow) * H_DIM + c4;
    }
    const uint32_t s0 = smem_u32(fsm);
    const uint32_t dBase = s0 + (uint32_t)(arw * PCH + c4) * 4;

    // ---- ldmatrix lane addressing
    const int arow_l = (lane & 7) + ((lane >> 3) & 1) * 8;
    const int acol_l = ((lane >> 4) & 1) * 4;
    const uint32_t aA = s0 + (uint32_t)((wm * 64 + arow_l) * PCH + acol_l) * 4;
    const uint32_t aB = s0 + 128 * PCH * 4 + (uint32_t)((wn * 64 + arow_l) * PCH + acol_l) * 4;

    float acc[4][8][4];
    #pragma unroll
    for (int i = 0; i < 4; i++)
        #pragma unroll
        for (int j = 0; j < 8; j++)
            #pragma unroll
            for (int q = 0; q < 4; q++) acc[i][j][q] = 0.f;

    const int NK = H_DIM / 16;   // 64

    #pragma unroll
    for (int s = 0; s < 3; s++) {
        uint32_t so = s * STG_BYTES;
        int kb = s * 16;
        #pragma unroll
        for (int p = 0; p < 4; p++) {
            CP_ASYNC(dBase + so + p * 32 * PCH * 4, pA[p] + kb);
            CP_ASYNC(dBase + so + (128 + 32 * p) * PCH * 4, pW[p] + kb);
        }
        CP_COMMIT();
    }

    for (int kt = 0; kt < NK; kt++) {
        CP_WAIT2();
        __syncthreads();
        if (kt + 3 < NK) {
            uint32_t so = ((kt + 3) & 3) * STG_BYTES;
            int kb = (kt + 3) * 16;
            #pragma unroll
            for (int p = 0; p < 4; p++) {
                CP_ASYNC(dBase + so + p * 32 * PCH * 4, pA[p] + kb);
                CP_ASYNC(dBase + so + (128 + 32 * p) * PCH * 4, pW[p] + kb);
            }
        }
        CP_COMMIT();

        const uint32_t so = (kt & 3) * STG_BYTES;
        #pragma unroll
        for (int k8 = 0; k8 < 2; k8++) {
            // B fragments for 4 n16-blocks; ldsm x4: b0=(n0-7,k0-3) b1=(n8-15,k0-3) b2=(n0-7,k4-7) b3=(n8-15,k4-7)
            uint32_t br[16];
            const uint32_t B0 = aB + so + k8 * 32;
            LDSM4(br[0],  br[1],  br[2],  br[3],  B0);
            LDSM4(br[4],  br[5],  br[6],  br[7],  B0 + 16 * PCH * 4);
            LDSM4(br[8],  br[9],  br[10], br[11], B0 + 32 * PCH * 4);
            LDSM4(br[12], br[13], br[14], br[15], B0 + 48 * PCH * 4);
            #pragma unroll
            for (int i = 0; i < 4; i++) {
                uint32_t a0, a1, a2, a3;
                LDSM4(a0, a1, a2, a3, aA + so + i * 16 * PCH * 4 + k8 * 32);
                #pragma unroll
                for (int q = 0; q < 4; q++) {
                    MMA_TF32(acc[i][2*q],   a0, a1, a2, a3, br[4*q],   br[4*q+2]);
                    MMA_TF32(acc[i][2*q+1], a0, a1, a2, a3, br[4*q+1], br[4*q+3]);
                }
            }
        }
    }
    CP_WAIT0();

    // -------- epilogue: stage gate/up at pitch 68 --------
    __syncthreads();
    float* stg = fsm;               // [128][68]
    float* stu = fsm + 8704;        // [128][68]; 69632 B <= 81920 B
    {
        float* dst = (wn == 0) ? stg : stu;
        const int g = lane >> 2, tg = lane & 3;
        #pragma unroll
        for (int i = 0; i < 4; i++) {
            int r = wm * 64 + i * 16 + g;
            #pragma unroll
            for (int j = 0; j < 8; j++) {
                int cc = j * 8 + tg * 2;
                *(float2*)&dst[r * 68 + cc]       = make_float2(acc[i][j][0], acc[i][j][1]);
                *(float2*)&dst[(r + 8) * 68 + cc] = make_float2(acc[i][j][2], acc[i][j][3]);
            }
        }
    }
    __syncthreads();
    #pragma unroll
    for (int it = 0; it < 16; it++) {      // 128 rows x 16 float4-chunks, 128 thr
        int q = tid + it * 128;
        int r = q >> 4, c = (q & 15) * 4;
        if (r < rows) {
            float4 o;
            o.x = t32(silu_mul(stg[r*68+c+0], stu[r*68+c+0]));
            o.y = t32(silu_mul(stg[r*68+c+1], stu[r*68+c+1]));
            o.z = t32(silu_mul(stg[r*68+c+2], stu[r*68+c+2]));
            o.w = t32(silu_mul(stg[r*68+c+3], stu[r*68+c+3]));
            *(float4*)(g_act + (size_t)(row0 + r) * F_DIM + bx * 64 + c) = o;
        }
    }
}

// ==================== GEMM2: y = coef * (act Wd^T) ====================
// grid(8, MAX_TILES), 128 thr (4 warps 2x2), 2 CTAs/SM. CTA 128x128, K=512.
__global__ void __launch_bounds__(128, 2)
k_gemm2(const float* __restrict__ unused) {
    int tile = blockIdx.y;
    if (tile >= g_num_tiles) return;
    const int e = g_tile_e[tile], row0 = g_tile_row[tile], rows = g_tile_rows[tile];
    const int bx = blockIdx.x;

    extern __shared__ __align__(16) float fsm[];
    __shared__ float s_w[BM];

    const int tid  = threadIdx.x;
    const int warp = tid >> 5, lane = tid & 31;
    const int wm = warp >> 1, wn = warp & 1;

    if (tid < BM) s_w[tid] = g_pair_w[row0 + ((tid < rows) ? tid : 0)];
    __syncthreads();

    const int arw = tid >> 2, c4 = (tid & 3) * 4;
    const float* pA[4];
    const float* pW[4];
    #pragma unroll
    for (int p = 0; p < 4; p++) {
        int rw = arw + 32 * p;
        int ar = row0 + ((rw < rows) ? rw : 0);
        pA[p] = g_act + (size_t)ar * F_DIM + c4;
        pW[p] = g_wd + ((size_t)e * H_DIM + bx * 128 + rw) * F_DIM + c4;
    }
    const uint32_t s0 = smem_u32(fsm);
    const uint32_t dBase = s0 + (uint32_t)(arw * PCH + c4) * 4;

    const int arow_l = (lane & 7) + ((lane >> 3) & 1) * 8;
    const int acol_l = ((lane >> 4) & 1) * 4;
    const uint32_t aA = s0 + (uint32_t)((wm * 64 + arow_l) * PCH + acol_l) * 4;
    const uint32_t aB = s0 + 128 * PCH * 4 + (uint32_t)((wn * 64 + arow_l) * PCH + acol_l) * 4;

    float acc[4][8][4];
    #pragma unroll
    for (int i = 0; i < 4; i++)
        #pragma unroll
        for (int j = 0; j < 8; j++)
            #pragma unroll
            for (int q = 0; q < 4; q++) acc[i][j][q] = 0.f;

    const int NK = F_DIM / 16;   // 32

    #pragma unroll
    for (int s = 0; s < 3; s++) {
        uint32_t so = s * STG_BYTES;
        int kb = s * 16;
        #pragma unroll
        for (int p = 0; p < 4; p++) {
            CP_ASYNC(dBase + so + p * 32 * PCH * 4, pA[p] + kb);
            CP_ASYNC(dBase + so + (128 + 32 * p) * PCH * 4, pW[p] + kb);
        }
        CP_COMMIT();
    }

    for (int kt = 0; kt < NK; kt++) {
        CP_WAIT2();
        __syncthreads();
        if (kt + 3 < NK) {
            uint32_t so = ((kt + 3) & 3) * STG_BYTES;
            int kb = (kt + 3) * 16;
            #pragma unroll
            for (int p = 0; p < 4; p++) {
                CP_ASYNC(dBase + so + p * 32 * PCH * 4, pA[p] + kb);
                CP_ASYNC(dBase + so + (128 + 32 * p) * PCH * 4, pW[p] + kb);
            }
        }
        CP_COMMIT();

        const uint32_t so = (kt & 3) * STG_BYTES;
        #pragma unroll
        for (int k8 = 0; k8 < 2; k8++) {
            uint32_t br[16];
            const uint32_t B0 = aB + so + k8 * 32;
            LDSM4(br[0],  br[1],  br[2],  br[3],  B0);
            LDSM4(br[4],  br[5],  br[6],  br[7],  B0 + 16 * PCH * 4);
            LDSM4(br[8],  br[9],  br[10], br[11], B0 + 32 * PCH * 4);
            LDSM4(br[12], br[13], br[14], br[15], B0 + 48 * PCH * 4);
            #pragma unroll
            for (int i = 0; i < 4; i++) {
                uint32_t a0, a1, a2, a3;
                LDSM4(a0, a1, a2, a3, aA + so + i * 16 * PCH * 4 + k8 * 32);
                #pragma unroll
                for (int q = 0; q < 4; q++) {
                    MMA_TF32(acc[i][2*q],   a0, a1, a2, a3, br[4*q],   br[4*q+2]);
                    MMA_TF32(acc[i][2*q+1], a0, a1, a2, a3, br[4*q+1], br[4*q+3]);
                }
            }
        }
    }
    CP_WAIT0();

    // -------- epilogue: stage 128x128 (pitch 132), fold coef --------
    __syncthreads();
    float* sty = fsm;   // [128][132] = 67584 B
    {
        const int g = lane >> 2, tg = lane & 3;
        #pragma unroll
        for (int i = 0; i < 4; i++) {
            int r = wm * 64 + i * 16 + g;
            #pragma unroll
            for (int j = 0; j < 8; j++) {
                int cc = wn * 64 + j * 8 + tg * 2;
                *(float2*)&sty[r * 132 + cc]       = make_float2(acc[i][j][0], acc[i][j][1]);
                *(float2*)&sty[(r + 8) * 132 + cc] = make_float2(acc[i][j][2], acc[i][j][3]);
            }
        }
    }
    __syncthreads();
    #pragma unroll
    for (int it = 0; it < 32; it++) {      // 128 rows x 32 float4-chunks, 128 thr
        int q = tid + it * 128;
        int r = q >> 5, c = (q & 31) * 4;
        if (r < rows) {
            float coef = s_w[r];
            float4 o;
            o.x = coef * sty[r*132+c+0];
            o.y = coef * sty[r*132+c+1];
            o.z = coef * sty[r*132+c+2];
            o.w = coef * sty[r*132+c+3];
            *(float4*)(g_y + (size_t)(row0 + r) * H_DIM + bx * 128 + c) = o;
        }
    }
}

// -------------------- combine: out[t] = y[pos0] + y[pos1] --------------------
__global__ void k_combine(float* __restrict__ out) {
    int idx = blockIdx.x * 256 + threadIdx.x;
    int t = idx >> 8;
    int c = idx & 255;
    int p0 = g_pos_of[2 * t], p1 = g_pos_of[2 * t + 1];
    const float4* y = (const float4*)g_y;
    float4 a = y[(size_t)p0 * (H_DIM / 4) + c];
    float4 b = y[(size_t)p1 * (H_DIM / 4) + c];
    ((float4*)out)[idx] = make_float4(a.x + b.x, a.y + b.y, a.z + b.z, a.w + b.w);
}

// -------------------- launch --------------------
extern "C" void kernel_launch(void* const* d_in, const int* in_sizes, int n_in,
                              void* d_out, int out_size) {
    const float* hidden   = (const float*)d_in[0];
    const float* topk_w   = (const float*)d_in[1];
    const int*   topk_ids = (const int*)d_in[2];
    const float* w_gu     = (const float*)d_in[3];
    const float* w_d      = (const float*)d_in[4];
    float* out = (float*)d_out;

    cudaFuncSetAttribute(k_gemm1, cudaFuncAttributeMaxDynamicSharedMemorySize, SMEM_BYTES);
    cudaFuncSetAttribute(k_gemm2, cudaFuncAttributeMaxDynamicSharedMemorySize, SMEM_BYTES);

    k_round_all<<<N4_ALL / 256, 256>>>(hidden, w_gu, w_d);          // launch 1
    k_route<<<1, 1024>>>(topk_ids);                                 // launch 2
    k_scatter<<<TK / 256, 256>>>(topk_ids, topk_w);                 // launch 3
    k_gemm1<<<dim3(8, MAX_TILES), 128, SMEM_BYTES>>>(hidden);       // launch 4 (ncu slot)
    k_gemm2<<<dim3(8, MAX_TILES), 128, SMEM_BYTES>>>(w_d);          // launch 5
    k_combine<<<(T_TOK * H_DIM / 4) / 256, 256>>>(out);             // launch 6
}

// round 13
// speedup vs baseline: 1.1761x; 1.1761x over previous
#include <cuda_runtime.h>
#include <cstdint>
#include <math.h>

#define T_TOK 16384
#define H_DIM 1024
#define F_DIM 512
#define E_NUM 64
#define TK    (T_TOK * 2)            // 32768 routed pairs
#define BM    128
#define MAX_TILES (TK / BM + E_NUM)  // 320
#define PCH   20                     // f32 smem pitch: conflict-free LDSM

// -------------------- static device scratch --------------------
__device__ int   g_offset[E_NUM];
__device__ int   g_cursor[E_NUM];
__device__ int   g_pair_token[TK];
__device__ float g_pair_w[TK];
__device__ int   g_pos_of[TK];
__device__ int   g_num_tiles;
__device__ int   g_tile_e[MAX_TILES];
__device__ int   g_tile_row[MAX_TILES];
__device__ int   g_tile_rows[MAX_TILES];

__device__ __align__(16) float g_act[(size_t)TK * F_DIM];   // tf32-rounded by gemm1
__device__ __align__(16) float g_y  [(size_t)TK * H_DIM];

// -------------------- helpers --------------------
__device__ __forceinline__ float t32(float x) {
    uint32_t u;
    asm("cvt.rna.tf32.f32 %0, %1;" : "=r"(u) : "f"(x));
    return __uint_as_float(u);
}
__device__ __forceinline__ uint32_t t32u(uint32_t x) {
    uint32_t u;
    asm("cvt.rna.tf32.f32 %0, %1;" : "=r"(u) : "f"(__uint_as_float(x)));
    return u;
}
__device__ __forceinline__ float silu_mul(float g, float u) {
    return g / (1.f + __expf(-g)) * u;
}
__device__ __forceinline__ uint32_t smem_u32(const void* p) {
    uint32_t a;
    asm("{ .reg .u64 t; cvta.to.shared.u64 t, %1; cvt.u32.u64 %0, t; }" : "=r"(a) : "l"(p));
    return a;
}

#define CP_ASYNC(dst, src) \
    asm volatile("cp.async.cg.shared.global [%0], [%1], 16;" :: "r"(dst), "l"(src))
#define CP_COMMIT() asm volatile("cp.async.commit_group;" ::: "memory")
#define CP_WAIT2()  asm volatile("cp.async.wait_group 2;" ::: "memory")
#define CP_WAIT0()  asm volatile("cp.async.wait_group 0;" ::: "memory")

#define LDSM4(r0, r1, r2, r3, addr) \
    asm volatile("ldmatrix.sync.aligned.m8n8.x4.shared.b16 {%0,%1,%2,%3}, [%4];" \
        : "=r"(r0), "=r"(r1), "=r"(r2), "=r"(r3) : "r"(addr))

#define MMA_TF32(c, a0, a1, a2, a3, b0, b1) \
    asm volatile("mma.sync.aligned.m16n8k8.row.col.f32.tf32.tf32.f32 " \
        "{%0,%1,%2,%3}, {%4,%5,%6,%7}, {%8,%9}, {%0,%1,%2,%3};" \
        : "+f"((c)[0]), "+f"((c)[1]), "+f"((c)[2]), "+f"((c)[3]) \
        : "r"(a0), "r"(a1), "r"(a2), "r"(a3), "r"(b0), "r"(b1))

// stage (f32): A [128][PCH] @ 0 ; W [128][PCH] @ 10240 B. Stage 20480 B x 4.
#define STG_BYTES 20480
#define SMEM_BYTES 81920

// -------------------- routing --------------------
__global__ void k_route(const int* __restrict__ ids) {
    __shared__ int hist[E_NUM];
    int tid = threadIdx.x;
    if (tid < E_NUM) hist[tid] = 0;
    __syncthreads();
    for (int i = tid; i < TK; i += 1024) atomicAdd(&hist[ids[i]], 1);
    __syncthreads();
    if (tid == 0) {
        int off = 0, nt = 0;
        for (int e = 0; e < E_NUM; e++) {
            g_offset[e] = off; g_cursor[e] = 0;
            int c = hist[e];
            for (int r = 0; r < c; r += BM) {
                g_tile_e[nt] = e;
                g_tile_row[nt] = off + r;
                g_tile_rows[nt] = (c - r < BM) ? (c - r) : BM;
                nt++;
            }
            off += c;
        }
        g_num_tiles = nt;
    }
}
__global__ void k_scatter(const int* __restrict__ ids, const float* __restrict__ w) {
    int i = blockIdx.x * blockDim.x + threadIdx.x;
    if (i < TK) {
        int e = ids[i];
        int pos = g_offset[e] + atomicAdd(&g_cursor[e], 1);
        g_pair_token[pos] = i >> 1;
        g_pair_w[pos] = w[i];
        g_pos_of[i] = pos;
    }
}

// ==================== GEMM1: act = silu(X Wg^T) * (X Wu^T) ====================
// grid(8, MAX_TILES), 256 thr (8 warps 2x4), 2 CTAs/SM.
// CTA 128 rows x (64 gate + 64 up). Warp tile 64x32 (tf32 m16n8k8). K=1024.
// Inputs unrounded; fragments rounded in-register with cvt.rna.tf32.
__global__ void __launch_bounds__(256, 2)
k_gemm1(const float* __restrict__ hidden, const float* __restrict__ w_gu) {
    int tile = blockIdx.y;
    if (tile >= g_num_tiles) return;
    const int e = g_tile_e[tile], row0 = g_tile_row[tile], rows = g_tile_rows[tile];
    const int bx = blockIdx.x;

    extern __shared__ __align__(16) float fsm[];
    __shared__ int s_tok[BM];

    const int tid  = threadIdx.x;
    const int warp = tid >> 5, lane = tid & 31;
    const int wm = warp >> 2, wn = warp & 3;

    if (tid < BM) s_tok[tid] = g_pair_token[row0 + ((tid < rows) ? tid : 0)];
    __syncthreads();

    // ---- cp.async mapping: per thread 4 chunks (A r, A r+64, W gate r, W up r)
    const int arw = tid >> 2, c4 = (tid & 3) * 4;       // arw in 0..63
    const int grow0 = bx * 64 + arw;                    // gate row -> smem W row arw
    const int grow1 = F_DIM + bx * 64 + arw;            // up row   -> smem W row arw+64
    const float* pA0 = hidden + (size_t)s_tok[arw] * H_DIM + c4;
    const float* pA1 = hidden + (size_t)s_tok[arw + 64] * H_DIM + c4;
    const float* pW0 = w_gu + ((size_t)e * 2 * F_DIM + grow0) * H_DIM + c4;
    const float* pW1 = w_gu + ((size_t)e * 2 * F_DIM + grow1) * H_DIM + c4;
    const uint32_t s0 = smem_u32(fsm);
    const uint32_t dA0 = s0 + (uint32_t)(arw * PCH + c4) * 4;
    const uint32_t dA1 = dA0 + 64 * PCH * 4;
    const uint32_t dW0 = dA0 + 128 * PCH * 4;
    const uint32_t dW1 = dW0 + 64 * PCH * 4;

    // ---- ldmatrix lane addressing
    const int arow_l = (lane & 7) + ((lane >> 3) & 1) * 8;
    const int acol_l = ((lane >> 4) & 1) * 4;
    const uint32_t aA = s0 + (uint32_t)((wm * 64 + arow_l) * PCH + acol_l) * 4;
    const uint32_t aB = s0 + 128 * PCH * 4 + (uint32_t)((wn * 32 + arow_l) * PCH + acol_l) * 4;

    float acc[4][4][4];
    #pragma unroll
    for (int i = 0; i < 4; i++)
        #pragma unroll
        for (int j = 0; j < 4; j++)
            #pragma unroll
            for (int q = 0; q < 4; q++) acc[i][j][q] = 0.f;

    const int NK = H_DIM / 16;   // 64

    #pragma unroll
    for (int s = 0; s < 3; s++) {
        uint32_t so = s * STG_BYTES;
        int kb = s * 16;
        CP_ASYNC(dA0 + so, pA0 + kb);
        CP_ASYNC(dA1 + so, pA1 + kb);
        CP_ASYNC(dW0 + so, pW0 + kb);
        CP_ASYNC(dW1 + so, pW1 + kb);
        CP_COMMIT();
    }

    for (int kt = 0; kt < NK; kt++) {
        CP_WAIT2();
        __syncthreads();
        if (kt + 3 < NK) {
            uint32_t so = ((kt + 3) & 3) * STG_BYTES;
            int kb = (kt + 3) * 16;
            CP_ASYNC(dA0 + so, pA0 + kb);
            CP_ASYNC(dA1 + so, pA1 + kb);
            CP_ASYNC(dW0 + so, pW0 + kb);
            CP_ASYNC(dW1 + so, pW1 + kb);
        }
        CP_COMMIT();

        const uint32_t so = (kt & 3) * STG_BYTES;
        const uint32_t A0 = aA + so, B0 = aB + so;
        #pragma unroll
        for (int k8 = 0; k8 < 2; k8++) {
            // ldsm x4 on B: b0=(n0-7,k0-3) b1=(n8-15,k0-3) b2=(n0-7,k4-7) b3=(n8-15,k4-7)
            uint32_t b0, b1, b2, b3, b4, b5, b6, b7;
            LDSM4(b0, b1, b2, b3, B0 + k8 * 32);
            LDSM4(b4, b5, b6, b7, B0 + 16 * PCH * 4 + k8 * 32);
            b0 = t32u(b0); b1 = t32u(b1); b2 = t32u(b2); b3 = t32u(b3);
            b4 = t32u(b4); b5 = t32u(b5); b6 = t32u(b6); b7 = t32u(b7);
            #pragma unroll
            for (int i = 0; i < 4; i++) {
                uint32_t a0, a1, a2, a3;
                LDSM4(a0, a1, a2, a3, A0 + i * 16 * PCH * 4 + k8 * 32);
                a0 = t32u(a0); a1 = t32u(a1); a2 = t32u(a2); a3 = t32u(a3);
                // mma B operands: (k0-3, k4-7) of the SAME n-block
                MMA_TF32(acc[i][0], a0, a1, a2, a3, b0, b2);
                MMA_TF32(acc[i][1], a0, a1, a2, a3, b1, b3);
                MMA_TF32(acc[i][2], a0, a1, a2, a3, b4, b6);
                MMA_TF32(acc[i][3], a0, a1, a2, a3, b5, b7);
            }
        }
    }
    CP_WAIT0();

    // -------- epilogue: stage gate/up at pitch 68 --------
    __syncthreads();
    float* stg = fsm;               // [128][68]
    float* stu = fsm + 8704;        // [128][68]; 69632 B <= 81920 B
    {
        float* dst = (wn < 2) ? stg : stu;
        const int lcb = (wn & 1) * 32;
        const int g = lane >> 2, tg = lane & 3;
        #pragma unroll
        for (int i = 0; i < 4; i++) {
            int r = wm * 64 + i * 16 + g;
            #pragma unroll
            for (int j = 0; j < 4; j++) {
                int cc = lcb + j * 8 + tg * 2;
                *(float2*)&dst[r * 68 + cc]       = make_float2(acc[i][j][0], acc[i][j][1]);
                *(float2*)&dst[(r + 8) * 68 + cc] = make_float2(acc[i][j][2], acc[i][j][3]);
            }
        }
    }
    __syncthreads();
    #pragma unroll
    for (int it = 0; it < 8; it++) {       // 128 rows x 16 float4-chunks
        int q = tid + it * 256;
        int r = q >> 4, c = (q & 15) * 4;
        if (r < rows) {
            float4 o;
            o.x = t32(silu_mul(stg[r*68+c+0], stu[r*68+c+0]));
            o.y = t32(silu_mul(stg[r*68+c+1], stu[r*68+c+1]));
            o.z = t32(silu_mul(stg[r*68+c+2], stu[r*68+c+2]));
            o.w = t32(silu_mul(stg[r*68+c+3], stu[r*68+c+3]));
            *(float4*)(g_act + (size_t)(row0 + r) * F_DIM + bx * 64 + c) = o;
        }
    }
}

// ==================== GEMM2: y = coef * (act Wd^T) ====================
// grid(8, MAX_TILES), 256 thr, 2 CTAs/SM. CTA 128x128, K=512.
// A (g_act) pre-rounded; only B fragments need cvt.
__global__ void __launch_bounds__(256, 2)
k_gemm2(const float* __restrict__ w_d) {
    int tile = blockIdx.y;
    if (tile >= g_num_tiles) return;
    const int e = g_tile_e[tile], row0 = g_tile_row[tile], rows = g_tile_rows[tile];
    const int bx = blockIdx.x;

    extern __shared__ __align__(16) float fsm[];
    __shared__ float s_w[BM];

    const int tid  = threadIdx.x;
    const int warp = tid >> 5, lane = tid & 31;
    const int wm = warp >> 2, wn = warp & 3;

    if (tid < BM) s_w[tid] = g_pair_w[row0 + ((tid < rows) ? tid : 0)];
    __syncthreads();

    const int arw = tid >> 2, c4 = (tid & 3) * 4;
    const int ar0 = row0 + ((arw < rows) ? arw : 0);
    const int ar1 = row0 + ((arw + 64 < rows) ? arw + 64 : 0);
    const float* pA0 = g_act + (size_t)ar0 * F_DIM + c4;
    const float* pA1 = g_act + (size_t)ar1 * F_DIM + c4;
    const float* pW0 = w_d + ((size_t)e * H_DIM + bx * 128 + arw) * F_DIM + c4;
    const float* pW1 = pW0 + (size_t)64 * F_DIM;
    const uint32_t s0 = smem_u32(fsm);
    const uint32_t dA0 = s0 + (uint32_t)(arw * PCH + c4) * 4;
    const uint32_t dA1 = dA0 + 64 * PCH * 4;
    const uint32_t dW0 = dA0 + 128 * PCH * 4;
    const uint32_t dW1 = dW0 + 64 * PCH * 4;

    const int arow_l = (lane & 7) + ((lane >> 3) & 1) * 8;
    const int acol_l = ((lane >> 4) & 1) * 4;
    const uint32_t aA = s0 + (uint32_t)((wm * 64 + arow_l) * PCH + acol_l) * 4;
    const uint32_t aB = s0 + 128 * PCH * 4 + (uint32_t)((wn * 32 + arow_l) * PCH + acol_l) * 4;

    float acc[4][4][4];
    #pragma unroll
    for (int i = 0; i < 4; i++)
        #pragma unroll
        for (int j = 0; j < 4; j++)
            #pragma unroll
            for (int q = 0; q < 4; q++) acc[i][j][q] = 0.f;

    const int NK = F_DIM / 16;   // 32

    #pragma unroll
    for (int s = 0; s < 3; s++) {
        uint32_t so = s * STG_BYTES;
        int kb = s * 16;
        CP_ASYNC(dA0 + so, pA0 + kb);
        CP_ASYNC(dA1 + so, pA1 + kb);
        CP_ASYNC(dW0 + so, pW0 + kb);
        CP_ASYNC(dW1 + so, pW1 + kb);
        CP_COMMIT();
    }

    for (int kt = 0; kt < NK; kt++) {
        CP_WAIT2();
        __syncthreads();
        if (kt + 3 < NK) {
            uint32_t so = ((kt + 3) & 3) * STG_BYTES;
            int kb = (kt + 3) * 16;
            CP_ASYNC(dA0 + so, pA0 + kb);
            CP_ASYNC(dA1 + so, pA1 + kb);
            CP_ASYNC(dW0 + so, pW0 + kb);
            CP_ASYNC(dW1 + so, pW1 + kb);
        }
        CP_COMMIT();

        const uint32_t so = (kt & 3) * STG_BYTES;
        const uint32_t A0 = aA + so, B0 = aB + so;
        #pragma unroll
        for (int k8 = 0; k8 < 2; k8++) {
            uint32_t b0, b1, b2, b3, b4, b5, b6, b7;
            LDSM4(b0, b1, b2, b3, B0 + k8 * 32);
            LDSM4(b4, b5, b6, b7, B0 + 16 * PCH * 4 + k8 * 32);
            b0 = t32u(b0); b1 = t32u(b1); b2 = t32u(b2); b3 = t32u(b3);
            b4 = t32u(b4); b5 = t32u(b5); b6 = t32u(b6); b7 = t32u(b7);
            #pragma unroll
            for (int i = 0; i < 4; i++) {
                uint32_t a0, a1, a2, a3;
                LDSM4(a0, a1, a2, a3, A0 + i * 16 * PCH * 4 + k8 * 32);
                MMA_TF32(acc[i][0], a0, a1, a2, a3, b0, b2);
                MMA_TF32(acc[i][1], a0, a1, a2, a3, b1, b3);
                MMA_TF32(acc[i][2], a0, a1, a2, a3, b4, b6);
                MMA_TF32(acc[i][3], a0, a1, a2, a3, b5, b7);
            }
        }
    }
    CP_WAIT0();

    // -------- epilogue: stage 128x128 (pitch 132), fold coef --------
    __syncthreads();
    float* sty = fsm;   // [128][132] = 67584 B
    {
        const int g = lane >> 2, tg = lane & 3;
        #pragma unroll
        for (int i = 0; i < 4; i++) {
            int r = wm * 64 + i * 16 + g;
            #pragma unroll
            for (int j = 0; j < 4; j++) {
                int cc = wn * 32 + j * 8 + tg * 2;
                *(float2*)&sty[r * 132 + cc]       = make_float2(acc[i][j][0], acc[i][j][1]);
                *(float2*)&sty[(r + 8) * 132 + cc] = make_float2(acc[i][j][2], acc[i][j][3]);
            }
        }
    }
    __syncthreads();
    #pragma unroll
    for (int it = 0; it < 16; it++) {      // 128 rows x 32 float4-chunks
        int q = tid + it * 256;
        int r = q >> 5, c = (q & 31) * 4;
        if (r < rows) {
            float coef = s_w[r];
            float4 o;
            o.x = coef * sty[r*132+c+0];
            o.y = coef * sty[r*132+c+1];
            o.z = coef * sty[r*132+c+2];
            o.w = coef * sty[r*132+c+3];
            *(float4*)(g_y + (size_t)(row0 + r) * H_DIM + bx * 128 + c) = o;
        }
    }
}

// -------------------- combine: out[t] = y[pos0] + y[pos1] --------------------
__global__ void k_combine(float* __restrict__ out) {
    int idx = blockIdx.x * 256 + threadIdx.x;
    int t = idx >> 8;
    int c = idx & 255;
    int p0 = g_pos_of[2 * t], p1 = g_pos_of[2 * t + 1];
    const float4* y = (const float4*)g_y;
    float4 a = y[(size_t)p0 * (H_DIM / 4) + c];
    float4 b = y[(size_t)p1 * (H_DIM / 4) + c];
    ((float4*)out)[idx] = make_float4(a.x + b.x, a.y + b.y, a.z + b.z, a.w + b.w);
}

// -------------------- launch --------------------
extern "C" void kernel_launch(void* const* d_in, const int* in_sizes, int n_in,
                              void* d_out, int out_size) {
    const float* hidden   = (const float*)d_in[0];
    const float* topk_w   = (const float*)d_in[1];
    const int*   topk_ids = (const int*)d_in[2];
    const float* w_gu     = (const float*)d_in[3];
    const float* w_d      = (const float*)d_in[4];
    float* out = (float*)d_out;

    cudaFuncSetAttribute(k_gemm1, cudaFuncAttributeMaxDynamicSharedMemorySize, SMEM_BYTES);
    cudaFuncSetAttribute(k_gemm2, cudaFuncAttributeMaxDynamicSharedMemorySize, SMEM_BYTES);

    k_route<<<1, 1024>>>(topk_ids);                                     // launch 1
    k_scatter<<<TK / 256, 256>>>(topk_ids, topk_w);                     // launch 2
    k_gemm1<<<dim3(8, MAX_TILES), 256, SMEM_BYTES>>>(hidden, w_gu);     // launch 3
    k_gemm2<<<dim3(8, MAX_TILES), 256, SMEM_BYTES>>>(w_d);              // launch 4 (ncu slot)
    k_combine<<<(T_TOK * H_DIM / 4) / 256, 256>>>(out);                 // launch 5
}

// round 14
// speedup vs baseline: 1.1819x; 1.0050x over previous
#include <cuda_runtime.h>
#include <cstdint>
#include <math.h>

#define T_TOK 16384
#define H_DIM 1024
#define F_DIM 512
#define E_NUM 64
#define TK    (T_TOK * 2)            // 32768 routed pairs
#define BM    128
#define MAX_TILES (TK / BM + E_NUM)  // 320
#define PCH   36                     // f32 smem pitch for K=32 stages: conflict-free LDSM

// -------------------- static device scratch --------------------
__device__ int   g_offset[E_NUM];
__device__ int   g_cursor[E_NUM];
__device__ int   g_pair_token[TK];
__device__ float g_pair_w[TK];
__device__ int   g_pos_of[TK];
__device__ int   g_num_tiles;
__device__ int   g_tile_e[MAX_TILES];
__device__ int   g_tile_row[MAX_TILES];
__device__ int   g_tile_rows[MAX_TILES];

__device__ __align__(16) float g_act[(size_t)TK * F_DIM];   // tf32-rounded by gemm1
__device__ __align__(16) float g_y  [(size_t)TK * H_DIM];

// -------------------- helpers --------------------
__device__ __forceinline__ float t32(float x) {
    uint32_t u;
    asm("cvt.rna.tf32.f32 %0, %1;" : "=r"(u) : "f"(x));
    return __uint_as_float(u);
}
__device__ __forceinline__ uint32_t t32u(uint32_t x) {
    uint32_t u;
    asm("cvt.rna.tf32.f32 %0, %1;" : "=r"(u) : "f"(__uint_as_float(x)));
    return u;
}
__device__ __forceinline__ float silu_mul(float g, float u) {
    return g / (1.f + __expf(-g)) * u;
}
__device__ __forceinline__ uint32_t smem_u32(const void* p) {
    uint32_t a;
    asm("{ .reg .u64 t; cvta.to.shared.u64 t, %1; cvt.u32.u64 %0, t; }" : "=r"(a) : "l"(p));
    return a;
}

#define CP_ASYNC(dst, src) \
    asm volatile("cp.async.cg.shared.global [%0], [%1], 16;" :: "r"(dst), "l"(src))
#define CP_COMMIT() asm volatile("cp.async.commit_group;" ::: "memory")
#define CP_WAIT1()  asm volatile("cp.async.wait_group 1;" ::: "memory")
#define CP_WAIT0()  asm volatile("cp.async.wait_group 0;" ::: "memory")

#define LDSM4(r0, r1, r2, r3, addr) \
    asm volatile("ldmatrix.sync.aligned.m8n8.x4.shared.b16 {%0,%1,%2,%3}, [%4];" \
        : "=r"(r0), "=r"(r1), "=r"(r2), "=r"(r3) : "r"(addr))

#define MMA_TF32(c, a0, a1, a2, a3, b0, b1) \
    asm volatile("mma.sync.aligned.m16n8k8.row.col.f32.tf32.tf32.f32 " \
        "{%0,%1,%2,%3}, {%4,%5,%6,%7}, {%8,%9}, {%0,%1,%2,%3};" \
        : "+f"((c)[0]), "+f"((c)[1]), "+f"((c)[2]), "+f"((c)[3]) \
        : "r"(a0), "r"(a1), "r"(a2), "r"(a3), "r"(b0), "r"(b1))

// stage (f32): A rows 0..127, W rows 128..255, 32 floats/row @ pitch 36.
// stage = 256*36*4 = 36864 B; 3 stages = 110592 B
#define STG_BYTES 36864
#define SMEM_BYTES 110592

// -------------------- routing --------------------
__global__ void k_route(const int* __restrict__ ids) {
    __shared__ int hist[E_NUM];
    int tid = threadIdx.x;
    if (tid < E_NUM) hist[tid] = 0;
    __syncthreads();
    for (int i = tid; i < TK; i += 1024) atomicAdd(&hist[ids[i]], 1);
    __syncthreads();
    if (tid == 0) {
        int off = 0, nt = 0;
        for (int e = 0; e < E_NUM; e++) {
            g_offset[e] = off; g_cursor[e] = 0;
            int c = hist[e];
            for (int r = 0; r < c; r += BM) {
                g_tile_e[nt] = e;
                g_tile_row[nt] = off + r;
                g_tile_rows[nt] = (c - r < BM) ? (c - r) : BM;
                nt++;
            }
            off += c;
        }
        g_num_tiles = nt;
    }
}
__global__ void k_scatter(const int* __restrict__ ids, const float* __restrict__ w) {
    int i = blockIdx.x * blockDim.x + threadIdx.x;
    if (i < TK) {
        int e = ids[i];
        int pos = g_offset[e] + atomicAdd(&g_cursor[e], 1);
        g_pair_token[pos] = i >> 1;
        g_pair_w[pos] = w[i];
        g_pos_of[i] = pos;
    }
}

// ==================== GEMM1: act = silu(X Wg^T) * (X Wu^T) ====================
// grid(8, MAX_TILES), 256 thr (8 warps 2x4), 2 CTAs/SM.
// CTA 128 rows x (64 gate + 64 up). Warp tile 64x32. K=1024, K-stage=32, 3-ring.
__global__ void __launch_bounds__(256, 2)
k_gemm1(const float* __restrict__ hidden, const float* __restrict__ w_gu) {
    int tile = blockIdx.y;
    if (tile >= g_num_tiles) return;
    const int e = g_tile_e[tile], row0 = g_tile_row[tile], rows = g_tile_rows[tile];
    const int bx = blockIdx.x;

    extern __shared__ __align__(16) float fsm[];
    __shared__ int s_tok[BM];

    const int tid  = threadIdx.x;
    const int warp = tid >> 5, lane = tid & 31;
    const int wm = warp >> 2, wn = warp & 3;

    if (tid < BM) s_tok[tid] = g_pair_token[row0 + ((tid < rows) ? tid : 0)];
    __syncthreads();

    // ---- cp.async mapping: row8 = tid>>3 (0..31), c8 = (tid&7)*4
    const int row8 = tid >> 3, c8 = (tid & 7) * 4;
    const float* pA[4];
    #pragma unroll
    for (int p = 0; p < 4; p++)
        pA[p] = hidden + (size_t)s_tok[row8 + 32 * p] * H_DIM + c8;
    // W rows 0..63 = gate (grow = bx*64 + rw), 64..127 = up (F_DIM + bx*64 + rw-64)
    const float* pWg = w_gu + ((size_t)e * 2 * F_DIM + bx * 64 + row8) * H_DIM + c8;
    const float* pWu = w_gu + ((size_t)e * 2 * F_DIM + F_DIM + bx * 64 + row8) * H_DIM + c8;

    const uint32_t s0 = smem_u32(fsm);
    const uint32_t dA = s0 + (uint32_t)(row8 * PCH + c8) * 4;          // + p*32*PCH*4
    const uint32_t dW = s0 + (uint32_t)((128 + row8) * PCH + c8) * 4;  // + p*32*PCH*4

    // ---- ldmatrix lane addressing
    const int arow_l = (lane & 7) + ((lane >> 3) & 1) * 8;
    const int acol_l = ((lane >> 4) & 1) * 4;
    const uint32_t aA = s0 + (uint32_t)((wm * 64 + arow_l) * PCH + acol_l) * 4;
    const uint32_t aB = s0 + (uint32_t)((128 + wn * 32 + arow_l) * PCH + acol_l) * 4;

    float acc[4][4][4];
    #pragma unroll
    for (int i = 0; i < 4; i++)
        #pragma unroll
        for (int j = 0; j < 4; j++)
            #pragma unroll
            for (int q = 0; q < 4; q++) acc[i][j][q] = 0.f;

    const int NK = H_DIM / 32;   // 32

    // prologue: stages 0,1
    #pragma unroll
    for (int s = 0; s < 2; s++) {
        uint32_t so = s * STG_BYTES;
        int kb = s * 32;
        #pragma unroll
        for (int p = 0; p < 4; p++) {
            CP_ASYNC(dA + so + p * 32 * PCH * 4, pA[p] + kb);
        }
        #pragma unroll
        for (int p = 0; p < 2; p++) {
            CP_ASYNC(dW + so + p * 32 * PCH * 4, pWg + (size_t)p * 32 * H_DIM + kb);
            CP_ASYNC(dW + so + (64 + 32 * p) * PCH * 4, pWu + (size_t)p * 32 * H_DIM + kb);
        }
        CP_COMMIT();
    }

    for (int kt = 0; kt < NK; kt++) {
        CP_WAIT1();
        __syncthreads();
        if (kt + 2 < NK) {
            uint32_t so = ((kt + 2) % 3) * STG_BYTES;
            int kb = (kt + 2) * 32;
            #pragma unroll
            for (int p = 0; p < 4; p++) {
                CP_ASYNC(dA + so + p * 32 * PCH * 4, pA[p] + kb);
            }
            #pragma unroll
            for (int p = 0; p < 2; p++) {
                CP_ASYNC(dW + so + p * 32 * PCH * 4, pWg + (size_t)p * 32 * H_DIM + kb);
                CP_ASYNC(dW + so + (64 + 32 * p) * PCH * 4, pWu + (size_t)p * 32 * H_DIM + kb);
            }
        }
        CP_COMMIT();

        const uint32_t so = (kt % 3) * STG_BYTES;
        const uint32_t A0 = aA + so, B0 = aB + so;
        #pragma unroll
        for (int k8 = 0; k8 < 4; k8++) {
            // ldsm x4 on B: b0=(n0-7,k0-3) b1=(n8-15,k0-3) b2=(n0-7,k4-7) b3=(n8-15,k4-7)
            uint32_t b0, b1, b2, b3, b4, b5, b6, b7;
            LDSM4(b0, b1, b2, b3, B0 + k8 * 32);
            LDSM4(b4, b5, b6, b7, B0 + 16 * PCH * 4 + k8 * 32);
            b0 = t32u(b0); b1 = t32u(b1); b2 = t32u(b2); b3 = t32u(b3);
            b4 = t32u(b4); b5 = t32u(b5); b6 = t32u(b6); b7 = t32u(b7);
            #pragma unroll
            for (int i = 0; i < 4; i++) {
                uint32_t a0, a1, a2, a3;
                LDSM4(a0, a1, a2, a3, A0 + i * 16 * PCH * 4 + k8 * 32);
                a0 = t32u(a0); a1 = t32u(a1); a2 = t32u(a2); a3 = t32u(a3);
                MMA_TF32(acc[i][0], a0, a1, a2, a3, b0, b2);
                MMA_TF32(acc[i][1], a0, a1, a2, a3, b1, b3);
                MMA_TF32(acc[i][2], a0, a1, a2, a3, b4, b6);
                MMA_TF32(acc[i][3], a0, a1, a2, a3, b5, b7);
            }
        }
    }
    CP_WAIT0();

    // -------- epilogue: stage gate/up at pitch 68 --------
    __syncthreads();
    float* stg = fsm;               // [128][68]
    float* stu = fsm + 8704;        // [128][68]; 69632 B <= 110592 B
    {
        float* dst = (wn < 2) ? stg : stu;
        const int lcb = (wn & 1) * 32;
        const int g = lane >> 2, tg = lane & 3;
        #pragma unroll
        for (int i = 0; i < 4; i++) {
            int r = wm * 64 + i * 16 + g;
            #pragma unroll
            for (int j = 0; j < 4; j++) {
                int cc = lcb + j * 8 + tg * 2;
                *(float2*)&dst[r * 68 + cc]       = make_float2(acc[i][j][0], acc[i][j][1]);
                *(float2*)&dst[(r + 8) * 68 + cc] = make_float2(acc[i][j][2], acc[i][j][3]);
            }
        }
    }
    __syncthreads();
    #pragma unroll
    for (int it = 0; it < 8; it++) {       // 128 rows x 16 float4-chunks
        int q = tid + it * 256;
        int r = q >> 4, c = (q & 15) * 4;
        if (r < rows) {
            float4 o;
            o.x = t32(silu_mul(stg[r*68+c+0], stu[r*68+c+0]));
            o.y = t32(silu_mul(stg[r*68+c+1], stu[r*68+c+1]));
            o.z = t32(silu_mul(stg[r*68+c+2], stu[r*68+c+2]));
            o.w = t32(silu_mul(stg[r*68+c+3], stu[r*68+c+3]));
            *(float4*)(g_act + (size_t)(row0 + r) * F_DIM + bx * 64 + c) = o;
        }
    }
}

// ==================== GEMM2: y = coef * (act Wd^T) ====================
// grid(8, MAX_TILES), 256 thr, 2 CTAs/SM. CTA 128x128, K=512, K-stage=32, 3-ring.
__global__ void __launch_bounds__(256, 2)
k_gemm2(const float* __restrict__ w_d) {
    int tile = blockIdx.y;
    if (tile >= g_num_tiles) return;
    const int e = g_tile_e[tile], row0 = g_tile_row[tile], rows = g_tile_rows[tile];
    const int bx = blockIdx.x;

    extern __shared__ __align__(16) float fsm[];
    __shared__ float s_w[BM];

    const int tid  = threadIdx.x;
    const int warp = tid >> 5, lane = tid & 31;
    const int wm = warp >> 2, wn = warp & 3;

    if (tid < BM) s_w[tid] = g_pair_w[row0 + ((tid < rows) ? tid : 0)];
    __syncthreads();

    const int row8 = tid >> 3, c8 = (tid & 7) * 4;
    const float* pA[4];
    #pragma unroll
    for (int p = 0; p < 4; p++) {
        int r = row8 + 32 * p;
        int ar = row0 + ((r < rows) ? r : 0);
        pA[p] = g_act + (size_t)ar * F_DIM + c8;
    }
    const float* pW = w_d + ((size_t)e * H_DIM + bx * 128 + row8) * F_DIM + c8;

    const uint32_t s0 = smem_u32(fsm);
    const uint32_t dA = s0 + (uint32_t)(row8 * PCH + c8) * 4;
    const uint32_t dW = s0 + (uint32_t)((128 + row8) * PCH + c8) * 4;

    const int arow_l = (lane & 7) + ((lane >> 3) & 1) * 8;
    const int acol_l = ((lane >> 4) & 1) * 4;
    const uint32_t aA = s0 + (uint32_t)((wm * 64 + arow_l) * PCH + acol_l) * 4;
    const uint32_t aB = s0 + (uint32_t)((128 + wn * 32 + arow_l) * PCH + acol_l) * 4;

    float acc[4][4][4];
    #pragma unroll
    for (int i = 0; i < 4; i++)
        #pragma unroll
        for (int j = 0; j < 4; j++)
            #pragma unroll
            for (int q = 0; q < 4; q++) acc[i][j][q] = 0.f;

    const int NK = F_DIM / 32;   // 16

    #pragma unroll
    for (int s = 0; s < 2; s++) {
        uint32_t so = s * STG_BYTES;
        int kb = s * 32;
        #pragma unroll
        for (int p = 0; p < 4; p++) {
            CP_ASYNC(dA + so + p * 32 * PCH * 4, pA[p] + kb);
            CP_ASYNC(dW + so + p * 32 * PCH * 4, pW + (size_t)p * 32 * F_DIM + kb);
        }
        CP_COMMIT();
    }

    for (int kt = 0; kt < NK; kt++) {
        CP_WAIT1();
        __syncthreads();
        if (kt + 2 < NK) {
            uint32_t so = ((kt + 2) % 3) * STG_BYTES;
            int kb = (kt + 2) * 32;
            #pragma unroll
            for (int p = 0; p < 4; p++) {
                CP_ASYNC(dA + so + p * 32 * PCH * 4, pA[p] + kb);
                CP_ASYNC(dW + so + p * 32 * PCH * 4, pW + (size_t)p * 32 * F_DIM + kb);
            }
        }
        CP_COMMIT();

        const uint32_t so = (kt % 3) * STG_BYTES;
        const uint32_t A0 = aA + so, B0 = aB + so;
        #pragma unroll
        for (int k8 = 0; k8 < 4; k8++) {
            uint32_t b0, b1, b2, b3, b4, b5, b6, b7;
            LDSM4(b0, b1, b2, b3, B0 + k8 * 32);
            LDSM4(b4, b5, b6, b7, B0 + 16 * PCH * 4 + k8 * 32);
            b0 = t32u(b0); b1 = t32u(b1); b2 = t32u(b2); b3 = t32u(b3);
            b4 = t32u(b4); b5 = t32u(b5); b6 = t32u(b6); b7 = t32u(b7);
            #pragma unroll
            for (int i = 0; i < 4; i++) {
                uint32_t a0, a1, a2, a3;
                LDSM4(a0, a1, a2, a3, A0 + i * 16 * PCH * 4 + k8 * 32);
                MMA_TF32(acc[i][0], a0, a1, a2, a3, b0, b2);
                MMA_TF32(acc[i][1], a0, a1, a2, a3, b1, b3);
                MMA_TF32(acc[i][2], a0, a1, a2, a3, b4, b6);
                MMA_TF32(acc[i][3], a0, a1, a2, a3, b5, b7);
            }
        }
    }
    CP_WAIT0();

    // -------- epilogue: stage 128x128 (pitch 132), fold coef --------
    __syncthreads();
    float* sty = fsm;   // [128][132] = 67584 B <= 110592 B
    {
        const int g = lane >> 2, tg = lane & 3;
        #pragma unroll
        for (int i = 0; i < 4; i++) {
            int r = wm * 64 + i * 16 + g;
            #pragma unroll
            for (int j = 0; j < 4; j++) {
                int cc = wn * 32 + j * 8 + tg * 2;
                *(float2*)&sty[r * 132 + cc]       = make_float2(acc[i][j][0], acc[i][j][1]);
                *(float2*)&sty[(r + 8) * 132 + cc] = make_float2(acc[i][j][2], acc[i][j][3]);
            }
        }
    }
    __syncthreads();
    #pragma unroll
    for (int it = 0; it < 16; it++) {      // 128 rows x 32 float4-chunks
        int q = tid + it * 256;
        int r = q >> 5, c = (q & 31) * 4;
        if (r < rows) {
            float coef = s_w[r];
            float4 o;
            o.x = coef * sty[r*132+c+0];
            o.y = coef * sty[r*132+c+1];
            o.z = coef * sty[r*132+c+2];
            o.w = coef * sty[r*132+c+3];
            *(float4*)(g_y + (size_t)(row0 + r) * H_DIM + bx * 128 + c) = o;
        }
    }
}

// -------------------- combine: out[t] = y[pos0] + y[pos1] --------------------
__global__ void k_combine(float* __restrict__ out) {
    int idx = blockIdx.x * 256 + threadIdx.x;
    int t = idx >> 8;
    int c = idx & 255;
    int p0 = g_pos_of[2 * t], p1 = g_pos_of[2 * t + 1];
    const float4* y = (const float4*)g_y;
    float4 a = y[(size_t)p0 * (H_DIM / 4) + c];
    float4 b = y[(size_t)p1 * (H_DIM / 4) + c];
    ((float4*)out)[idx] = make_float4(a.x + b.x, a.y + b.y, a.z + b.z, a.w + b.w);
}

// -------------------- launch --------------------
extern "C" void kernel_launch(void* const* d_in, const int* in_sizes, int n_in,
                              void* d_out, int out_size) {
    const float* hidden   = (const float*)d_in[0];
    const float* topk_w   = (const float*)d_in[1];
    const int*   topk_ids = (const int*)d_in[2];
    const float* w_gu     = (const float*)d_in[3];
    const float* w_d      = (const float*)d_in[4];
    float* out = (float*)d_out;

    cudaFuncSetAttribute(k_gemm1, cudaFuncAttributeMaxDynamicSharedMemorySize, SMEM_BYTES);
    cudaFuncSetAttribute(k_gemm2, cudaFuncAttributeMaxDynamicSharedMemorySize, SMEM_BYTES);

    k_route<<<1, 1024>>>(topk_ids);                                     // launch 1
    k_scatter<<<TK / 256, 256>>>(topk_ids, topk_w);                     // launch 2
    k_gemm1<<<dim3(8, MAX_TILES), 256, SMEM_BYTES>>>(hidden, w_gu);     // launch 3
    k_gemm2<<<dim3(8, MAX_TILES), 256, SMEM_BYTES>>>(w_d);              // launch 4 (ncu slot)
    k_combine<<<(T_TOK * H_DIM / 4) / 256, 256>>>(out);                 // launch 5
}

// round 15
// speedup vs baseline: 1.2346x; 1.0445x over previous
#include <cuda_runtime.h>
#include <cstdint>
#include <math.h>

#define T_TOK 16384
#define H_DIM 1024
#define F_DIM 512
#define E_NUM 64
#define TK    (T_TOK * 2)            // 32768 routed pairs
#define BM    128
#define MAX_TILES (TK / BM + E_NUM)  // 320
#define PCH   20                     // f32 smem pitch (K=16 stages): conflict-free LDSM

// -------------------- static device scratch --------------------
__device__ int   g_offset[E_NUM];
__device__ int   g_cursor[E_NUM];
__device__ int   g_pair_token[TK];
__device__ float g_pair_w[TK];
__device__ int   g_pos_of[TK];
__device__ int   g_num_tiles;
__device__ int   g_tile_e[MAX_TILES];
__device__ int   g_tile_row[MAX_TILES];
__device__ int   g_tile_rows[MAX_TILES];

__device__ __align__(16) float g_hid[(size_t)T_TOK * H_DIM];  // tf32-rounded hidden
__device__ __align__(16) float g_act[(size_t)TK * F_DIM];     // tf32-rounded by gemm1
__device__ __align__(16) float g_y  [(size_t)TK * H_DIM];

// -------------------- helpers --------------------
__device__ __forceinline__ float t32(float x) {
    uint32_t u;
    asm("cvt.rna.tf32.f32 %0, %1;" : "=r"(u) : "f"(x));
    return __uint_as_float(u);
}
__device__ __forceinline__ uint32_t t32u(uint32_t x) {
    uint32_t u;
    asm("cvt.rna.tf32.f32 %0, %1;" : "=r"(u) : "f"(__uint_as_float(x)));
    return u;
}
__device__ __forceinline__ float silu_mul(float g, float u) {
    return g / (1.f + __expf(-g)) * u;
}
__device__ __forceinline__ uint32_t smem_u32(const void* p) {
    uint32_t a;
    asm("{ .reg .u64 t; cvta.to.shared.u64 t, %1; cvt.u32.u64 %0, t; }" : "=r"(a) : "l"(p));
    return a;
}

#define CP_ASYNC(dst, src) \
    asm volatile("cp.async.cg.shared.global [%0], [%1], 16;" :: "r"(dst), "l"(src))
#define CP_COMMIT() asm volatile("cp.async.commit_group;" ::: "memory")
#define CP_WAIT2()  asm volatile("cp.async.wait_group 2;" ::: "memory")
#define CP_WAIT0()  asm volatile("cp.async.wait_group 0;" ::: "memory")

#define LDSM4(r0, r1, r2, r3, addr) \
    asm volatile("ldmatrix.sync.aligned.m8n8.x4.shared.b16 {%0,%1,%2,%3}, [%4];" \
        : "=r"(r0), "=r"(r1), "=r"(r2), "=r"(r3) : "r"(addr))

#define MMA_TF32(c, a0, a1, a2, a3, b0, b1) \
    asm volatile("mma.sync.aligned.m16n8k8.row.col.f32.tf32.tf32.f32 " \
        "{%0,%1,%2,%3}, {%4,%5,%6,%7}, {%8,%9}, {%0,%1,%2,%3};" \
        : "+f"((c)[0]), "+f"((c)[1]), "+f"((c)[2]), "+f"((c)[3]) \
        : "r"(a0), "r"(a1), "r"(a2), "r"(a3), "r"(b0), "r"(b1))

// stage (f32): A rows 0..127, W rows 128..255, 16 floats/row @ pitch 20.
// stage = 256*20*4 = 20480 B; 4 stages = 81920 B
#define STG_BYTES 20480
#define SMEM_BYTES 81920

// -------------------- tf32 rounding of hidden (64 MB, ~18us) --------------------
__global__ void k_round_hid(const float* __restrict__ hidden) {
    size_t i = (size_t)blockIdx.x * 256 + threadIdx.x;   // float4 units
    float4 v = ((const float4*)hidden)[i];
    ((float4*)g_hid)[i] = make_float4(t32(v.x), t32(v.y), t32(v.z), t32(v.w));
}

// -------------------- routing --------------------
__global__ void k_route(const int* __restrict__ ids) {
    __shared__ int hist[E_NUM];
    int tid = threadIdx.x;
    if (tid < E_NUM) hist[tid] = 0;
    __syncthreads();
    for (int i = tid; i < TK; i += 1024) atomicAdd(&hist[ids[i]], 1);
    __syncthreads();
    if (tid == 0) {
        int off = 0, nt = 0;
        for (int e = 0; e < E_NUM; e++) {
            g_offset[e] = off; g_cursor[e] = 0;
            int c = hist[e];
            for (int r = 0; r < c; r += BM) {
                g_tile_e[nt] = e;
                g_tile_row[nt] = off + r;
                g_tile_rows[nt] = (c - r < BM) ? (c - r) : BM;
                nt++;
            }
            off += c;
        }
        g_num_tiles = nt;
    }
}
__global__ void k_scatter(const int* __restrict__ ids, const float* __restrict__ w) {
    int i = blockIdx.x * blockDim.x + threadIdx.x;
    if (i < TK) {
        int e = ids[i];
        int pos = g_offset[e] + atomicAdd(&g_cursor[e], 1);
        g_pair_token[pos] = i >> 1;
        g_pair_w[pos] = w[i];
        g_pos_of[i] = pos;
    }
}

// ==================== GEMM1: act = silu(X Wg^T) * (X Wu^T) ====================
// grid(8, MAX_TILES), 512 thr (16 warps 4x4), 2 CTAs/SM -> 32 warps/SM.
// CTA 128 rows x (64 gate + 64 up). Warp tile 32x32. K=1024, K-stage=16, 4-ring.
// A (g_hid) pre-rounded; B fragments cvt'd in-register.
__global__ void __launch_bounds__(512, 2)
k_gemm1(const float* __restrict__ w_gu) {
    int tile = blockIdx.y;
    if (tile >= g_num_tiles) return;
    const int e = g_tile_e[tile], row0 = g_tile_row[tile], rows = g_tile_rows[tile];
    const int bx = blockIdx.x;

    extern __shared__ __align__(16) float fsm[];
    __shared__ int s_tok[BM];

    const int tid  = threadIdx.x;
    const int warp = tid >> 5, lane = tid & 31;
    const int wm = warp >> 2, wn = warp & 3;

    if (tid < BM) s_tok[tid] = g_pair_token[row0 + ((tid < rows) ? tid : 0)];
    __syncthreads();

    // ---- cp.async: 2 chunks/thread. arow = tid>>2 (0..127), c4 = (tid&3)*4
    const int arw = tid >> 2, c4 = (tid & 3) * 4;
    const float* pA = g_hid + (size_t)s_tok[arw] * H_DIM + c4;
    const int grow = (arw < 64) ? (bx * 64 + arw) : (F_DIM + bx * 64 + (arw - 64));
    const float* pW = w_gu + ((size_t)e * 2 * F_DIM + grow) * H_DIM + c4;
    const uint32_t s0 = smem_u32(fsm);
    const uint32_t dA = s0 + (uint32_t)(arw * PCH + c4) * 4;
    const uint32_t dW = dA + 128 * PCH * 4;

    // ---- ldmatrix lane addressing
    const int arow_l = (lane & 7) + ((lane >> 3) & 1) * 8;
    const int acol_l = ((lane >> 4) & 1) * 4;
    const uint32_t aA = s0 + (uint32_t)((wm * 32 + arow_l) * PCH + acol_l) * 4;
    const uint32_t aB = s0 + (uint32_t)((128 + wn * 32 + arow_l) * PCH + acol_l) * 4;

    float acc[2][4][4];
    #pragma unroll
    for (int i = 0; i < 2; i++)
        #pragma unroll
        for (int j = 0; j < 4; j++)
            #pragma unroll
            for (int q = 0; q < 4; q++) acc[i][j][q] = 0.f;

    const int NK = H_DIM / 16;   // 64

    #pragma unroll
    for (int s = 0; s < 3; s++) {
        uint32_t so = s * STG_BYTES;
        int kb = s * 16;
        CP_ASYNC(dA + so, pA + kb);
        CP_ASYNC(dW + so, pW + kb);
        CP_COMMIT();
    }

    for (int kt = 0; kt < NK; kt++) {
        CP_WAIT2();
        __syncthreads();
        if (kt + 3 < NK) {
            uint32_t so = ((kt + 3) & 3) * STG_BYTES;
            int kb = (kt + 3) * 16;
            CP_ASYNC(dA + so, pA + kb);
            CP_ASYNC(dW + so, pW + kb);
        }
        CP_COMMIT();

        const uint32_t so = (kt & 3) * STG_BYTES;
        const uint32_t A0 = aA + so, B0 = aB + so;
        #pragma unroll
        for (int k8 = 0; k8 < 2; k8++) {
            // B: 32 cols = 2 LDSM4 (n 0-15, n 16-31); pairs (b0,b2),(b1,b3) per n16-block
            uint32_t bl0, bl1, bl2, bl3, bh0, bh1, bh2, bh3;
            LDSM4(bl0, bl1, bl2, bl3, B0 + k8 * 32);
            LDSM4(bh0, bh1, bh2, bh3, B0 + 16 * PCH * 4 + k8 * 32);
            bl0 = t32u(bl0); bl1 = t32u(bl1); bl2 = t32u(bl2); bl3 = t32u(bl3);
            bh0 = t32u(bh0); bh1 = t32u(bh1); bh2 = t32u(bh2); bh3 = t32u(bh3);
            // A: 32 rows = 2 LDSM4 (rows 0-15, 16-31); already tf32-rounded
            uint32_t a0, a1, a2, a3, a4, a5, a6, a7;
            LDSM4(a0, a1, a2, a3, A0 + k8 * 32);
            LDSM4(a4, a5, a6, a7, A0 + 16 * PCH * 4 + k8 * 32);
            MMA_TF32(acc[0][0], a0, a1, a2, a3, bl0, bl2);
            MMA_TF32(acc[0][1], a0, a1, a2, a3, bl1, bl3);
            MMA_TF32(acc[0][2], a0, a1, a2, a3, bh0, bh2);
            MMA_TF32(acc[0][3], a0, a1, a2, a3, bh1, bh3);
            MMA_TF32(acc[1][0], a4, a5, a6, a7, bl0, bl2);
            MMA_TF32(acc[1][1], a4, a5, a6, a7, bl1, bl3);
            MMA_TF32(acc[1][2], a4, a5, a6, a7, bh0, bh2);
            MMA_TF32(acc[1][3], a4, a5, a6, a7, bh1, bh3);
        }
    }
    CP_WAIT0();

    // -------- epilogue: stage gate/up at pitch 68 --------
    __syncthreads();
    float* stg = fsm;               // [128][68]
    float* stu = fsm + 8704;        // [128][68]; 69632 B <= 81920 B
    {
        float* dst = (wn < 2) ? stg : stu;
        const int lcb = (wn & 1) * 32;
        const int g = lane >> 2, tg = lane & 3;
        #pragma unroll
        for (int i = 0; i < 2; i++) {
            int r = wm * 32 + i * 16 + g;
            #pragma unroll
            for (int j = 0; j < 4; j++) {
                int cc = lcb + j * 8 + tg * 2;
                *(float2*)&dst[r * 68 + cc]       = make_float2(acc[i][j][0], acc[i][j][1]);
                *(float2*)&dst[(r + 8) * 68 + cc] = make_float2(acc[i][j][2], acc[i][j][3]);
            }
        }
    }
    __syncthreads();
    #pragma unroll
    for (int it = 0; it < 4; it++) {       // 128 rows x 16 float4-chunks, 512 thr
        int q = tid + it * 512;
        int r = q >> 4, c = (q & 15) * 4;
        if (r < rows) {
            float4 o;
            o.x = t32(silu_mul(stg[r*68+c+0], stu[r*68+c+0]));
            o.y = t32(silu_mul(stg[r*68+c+1], stu[r*68+c+1]));
            o.z = t32(silu_mul(stg[r*68+c+2], stu[r*68+c+2]));
            o.w = t32(silu_mul(stg[r*68+c+3], stu[r*68+c+3]));
            *(float4*)(g_act + (size_t)(row0 + r) * F_DIM + bx * 64 + c) = o;
        }
    }
}

// ==================== GEMM2: y = coef * (act Wd^T) ====================
// grid(8, MAX_TILES), 512 thr (16 warps 4x4), 2 CTAs/SM. CTA 128x128,
// warp tile 32x32, K=512, K-stage=16, 4-ring. A pre-rounded; B cvt.
__global__ void __launch_bounds__(512, 2)
k_gemm2(const float* __restrict__ w_d) {
    int tile = blockIdx.y;
    if (tile >= g_num_tiles) return;
    const int e = g_tile_e[tile], row0 = g_tile_row[tile], rows = g_tile_rows[tile];
    const int bx = blockIdx.x;

    extern __shared__ __align__(16) float fsm[];
    __shared__ float s_w[BM];

    const int tid  = threadIdx.x;
    const int warp = tid >> 5, lane = tid & 31;
    const int wm = warp >> 2, wn = warp & 3;

    if (tid < BM) s_w[tid] = g_pair_w[row0 + ((tid < rows) ? tid : 0)];
    __syncthreads();

    const int arw = tid >> 2, c4 = (tid & 3) * 4;
    const int ar = row0 + ((arw < rows) ? arw : 0);
    const float* pA = g_act + (size_t)ar * F_DIM + c4;
    const float* pW = w_d + ((size_t)e * H_DIM + bx * 128 + arw) * F_DIM + c4;
    const uint32_t s0 = smem_u32(fsm);
    const uint32_t dA = s0 + (uint32_t)(arw * PCH + c4) * 4;
    const uint32_t dW = dA + 128 * PCH * 4;

    const int arow_l = (lane & 7) + ((lane >> 3) & 1) * 8;
    const int acol_l = ((lane >> 4) & 1) * 4;
    const uint32_t aA = s0 + (uint32_t)((wm * 32 + arow_l) * PCH + acol_l) * 4;
    const uint32_t aB = s0 + (uint32_t)((128 + wn * 32 + arow_l) * PCH + acol_l) * 4;

    float acc[2][4][4];
    #pragma unroll
    for (int i = 0; i < 2; i++)
        #pragma unroll
        for (int j = 0; j < 4; j++)
            #pragma unroll
            for (int q = 0; q < 4; q++) acc[i][j][q] = 0.f;

    const int NK = F_DIM / 16;   // 32

    #pragma unroll
    for (int s = 0; s < 3; s++) {
        uint32_t so = s * STG_BYTES;
        int kb = s * 16;
        CP_ASYNC(dA + so, pA + kb);
        CP_ASYNC(dW + so, pW + kb);
        CP_COMMIT();
    }

    for (int kt = 0; kt < NK; kt++) {
        CP_WAIT2();
        __syncthreads();
        if (kt + 3 < NK) {
            uint32_t so = ((kt + 3) & 3) * STG_BYTES;
            int kb = (kt + 3) * 16;
            CP_ASYNC(dA + so, pA + kb);
            CP_ASYNC(dW + so, pW + kb);
        }
        CP_COMMIT();

        const uint32_t so = (kt & 3) * STG_BYTES;
        const uint32_t A0 = aA + so, B0 = aB + so;
        #pragma unroll
        for (int k8 = 0; k8 < 2; k8++) {
            uint32_t bl0, bl1, bl2, bl3, bh0, bh1, bh2, bh3;
            LDSM4(bl0, bl1, bl2, bl3, B0 + k8 * 32);
            LDSM4(bh0, bh1, bh2, bh3, B0 + 16 * PCH * 4 + k8 * 32);
            bl0 = t32u(bl0); bl1 = t32u(bl1); bl2 = t32u(bl2); bl3 = t32u(bl3);
            bh0 = t32u(bh0); bh1 = t32u(bh1); bh2 = t32u(bh2); bh3 = t32u(bh3);
            uint32_t a0, a1, a2, a3, a4, a5, a6, a7;
            LDSM4(a0, a1, a2, a3, A0 + k8 * 32);
            LDSM4(a4, a5, a6, a7, A0 + 16 * PCH * 4 + k8 * 32);
            MMA_TF32(acc[0][0], a0, a1, a2, a3, bl0, bl2);
            MMA_TF32(acc[0][1], a0, a1, a2, a3, bl1, bl3);
            MMA_TF32(acc[0][2], a0, a1, a2, a3, bh0, bh2);
            MMA_TF32(acc[0][3], a0, a1, a2, a3, bh1, bh3);
            MMA_TF32(acc[1][0], a4, a5, a6, a7, bl0, bl2);
            MMA_TF32(acc[1][1], a4, a5, a6, a7, bl1, bl3);
            MMA_TF32(acc[1][2], a4, a5, a6, a7, bh0, bh2);
            MMA_TF32(acc[1][3], a4, a5, a6, a7, bh1, bh3);
        }
    }
    CP_WAIT0();

    // -------- epilogue: stage 128x128 (pitch 132), fold coef --------
    __syncthreads();
    float* sty = fsm;   // [128][132] = 67584 B <= 81920 B
    {
        const int g = lane >> 2, tg = lane & 3;
        #pragma unroll
        for (int i = 0; i < 2; i++) {
            int r = wm * 32 + i * 16 + g;
            #pragma unroll
            for (int j = 0; j < 4; j++) {
                int cc = wn * 32 + j * 8 + tg * 2;
                *(float2*)&sty[r * 132 + cc]       = make_float2(acc[i][j][0], acc[i][j][1]);
                *(float2*)&sty[(r + 8) * 132 + cc] = make_float2(acc[i][j][2], acc[i][j][3]);
            }
        }
    }
    __syncthreads();
    #pragma unroll
    for (int it = 0; it < 8; it++) {       // 128 rows x 32 float4-chunks, 512 thr
        int q = tid + it * 512;
        int r = q >> 5, c = (q & 31) * 4;
        if (r < rows) {
            float coef = s_w[r];
            float4 o;
            o.x = coef * sty[r*132+c+0];
            o.y = coef * sty[r*132+c+1];
            o.z = coef * sty[r*132+c+2];
            o.w = coef * sty[r*132+c+3];
            *(float4*)(g_y + (size_t)(row0 + r) * H_DIM + bx * 128 + c) = o;
        }
    }
}

// -------------------- combine: out[t] = y[pos0] + y[pos1] --------------------
__global__ void k_combine(float* __restrict__ out) {
    int idx = blockIdx.x * 256 + threadIdx.x;
    int t = idx >> 8;
    int c = idx & 255;
    int p0 = g_pos_of[2 * t], p1 = g_pos_of[2 * t + 1];
    const float4* y = (const float4*)g_y;
    float4 a = y[(size_t)p0 * (H_DIM / 4) + c];
    float4 b = y[(size_t)p1 * (H_DIM / 4) + c];
    ((float4*)out)[idx] = make_float4(a.x + b.x, a.y + b.y, a.z + b.z, a.w + b.w);
}

// -------------------- launch --------------------
extern "C" void kernel_launch(void* const* d_in, const int* in_sizes, int n_in,
                              void* d_out, int out_size) {
    const float* hidden   = (const float*)d_in[0];
    const float* topk_w   = (const float*)d_in[1];
    const int*   topk_ids = (const int*)d_in[2];
    const float* w_gu     = (const float*)d_in[3];
    const float* w_d      = (const float*)d_in[4];
    float* out = (float*)d_out;

    cudaFuncSetAttribute(k_gemm1, cudaFuncAttributeMaxDynamicSharedMemorySize, SMEM_BYTES);
    cudaFuncSetAttribute(k_gemm2, cudaFuncAttributeMaxDynamicSharedMemorySize, SMEM_BYTES);

    k_round_hid<<<(T_TOK * H_DIM / 4) / 256, 256>>>(hidden);            // launch 1
    k_route<<<1, 1024>>>(topk_ids);                                     // launch 2
    k_scatter<<<TK / 256, 256>>>(topk_ids, topk_w);                     // launch 3
    k_gemm1<<<dim3(8, MAX_TILES), 512, SMEM_BYTES>>>(w_gu);             // launch 4 (ncu slot)
    k_gemm2<<<dim3(8, MAX_TILES), 512, SMEM_BYTES>>>(w_d);              // launch 5
    k_combine<<<(T_TOK * H_DIM / 4) / 256, 256>>>(out);                 // launch 6
}